// round 7
// baseline (speedup 1.0000x reference)
#include <cuda_runtime.h>
#include <stdint.h>

#define N_DET 1024
#define HW 40960
#define SIGMA 2.0f
#define KSPLIT 4
#define KSL (HW / KSPLIT)      // 10240 cols per split
#define NT 8                   // 128-row tile grid
#define STAGES 3
#define KC_BYTES 256           // s8 per row per chunk
#define NC (KSL / KC_BYTES)    // 40 chunks
#define ROW_STRIDE 272         // 256 + 16B pad -> conflict-free ldmatrix
#define SIDE_BYTES (128 * ROW_STRIDE)       // 34816
#define STAGE_BYTES (2 * SIDE_BYTES)        // 69632
#define SMEM_TOTAL (STAGES * STAGE_BYTES)   // 208896
#define N_CONV 1024
#define N_GEMM (36 * KSPLIT)   // 144
#define N_BLOCKS (N_CONV + N_GEMM)
#define T_STRIDE 132           // transpose buffer stride (floats): 16B-aligned rows

// ---- device scratch ----
__device__ __align__(16) signed char g_s8[(size_t)N_DET * HW];     // 40 MB
__device__ float g_sum[N_DET];
__device__ float g_part_T[KSPLIT][(size_t)N_DET * N_DET];          // 16 MB, [j][i]
__device__ float g_decay_T[(size_t)N_DET * N_DET];                 // 4 MB,  [j][i]
__device__ float g_comp2[N_DET];
__device__ int   g_ready[NT];                                      // conv completion counters

// ---------------------------------------------------------------------------
__device__ __forceinline__ uint32_t smem_u32(const void* p) {
    uint32_t a;
    asm("{ .reg .u64 t; cvta.to.shared.u64 t, %1; cvt.u32.u64 %0, t; }" : "=r"(a) : "l"(p));
    return a;
}
#define CP_ASYNC16(dst, src) \
    asm volatile("cp.async.cg.shared.global [%0], [%1], 16;" :: "r"((uint32_t)(dst)), "l"(src) : "memory")
#define CP_COMMIT() asm volatile("cp.async.commit_group;" ::: "memory")
#define CP_WAIT2()  asm volatile("cp.async.wait_group 2;" ::: "memory")

#define LDSM_X4(r0, r1, r2, r3, addr) \
    asm volatile("ldmatrix.sync.aligned.m8n8.x4.shared.b16 {%0,%1,%2,%3}, [%4];" \
        : "=r"(r0), "=r"(r1), "=r"(r2), "=r"(r3) : "r"(addr))
#define LDSM_X2(r0, r1, addr) \
    asm volatile("ldmatrix.sync.aligned.m8n8.x2.shared.b16 {%0,%1}, [%2];" \
        : "=r"(r0), "=r"(r1) : "r"(addr))
#define MMA_S8(d, a, b) \
    asm volatile("mma.sync.aligned.m16n8k32.row.col.s32.s8.s8.s32 " \
        "{%0,%1,%2,%3}, {%4,%5,%6,%7}, {%8,%9}, {%0,%1,%2,%3};" \
        : "+r"((d)[0]), "+r"((d)[1]), "+r"((d)[2]), "+r"((d)[3]) \
        : "r"((a)[0]), "r"((a)[1]), "r"((a)[2]), "r"((a)[3]), "r"((b)[0]), "r"((b)[1]))

// ---------------------------------------------------------------------------
// Fused kernel: 1024 convert blocks + 144 gemm blocks in one launch.
// bid order interleaves conv rowblocks with the gemm tiles they unblock:
//   segment r: [128 conv blocks for rows r*128..] [4*(r+1) gemm blocks (ti<=r, tj=r, ks)]
// ---------------------------------------------------------------------------
__global__ void __launch_bounds__(128, 1) fused_kernel(const float* __restrict__ seg) {
    extern __shared__ char smem[];
    int tid = threadIdx.x;

    // segment decode
    int bid = blockIdx.x;
    int r = 0;
    int rem = bid;
    while (rem >= 128 + 4 * (r + 1)) { rem -= 128 + 4 * (r + 1); ++r; }

    if (rem < 128) {
        // ---------------- convert block: one full mask row ----------------
        int row = r * 128 + rem;
        const float4* in4 = (const float4*)(seg + (size_t)row * HW);
        uint4* out = (uint4*)(g_s8 + (size_t)row * HW);
        int cnt = 0;
        #pragma unroll 4
        for (int u0 = 0; u0 < 20; ++u0) {          // 128 thr * 20 * 16 floats = 40960
            int u = u0 * 128 + tid;                // uint4 index 0..2559
            uint4 o;
            uint32_t* wp = (uint32_t*)&o;
            #pragma unroll
            for (int s = 0; s < 4; ++s) {
                float4 f = in4[u * 4 + s];
                uint32_t b0 = (f.x != 0.0f), b1 = (f.y != 0.0f),
                         b2 = (f.z != 0.0f), b3 = (f.w != 0.0f);
                cnt += b0 + b1 + b2 + b3;
                wp[s] = b0 | (b1 << 8) | (b2 << 16) | (b3 << 24);
            }
            out[u] = o;
        }
        #pragma unroll
        for (int o = 16; o; o >>= 1) cnt += __shfl_xor_sync(0xFFFFFFFFu, cnt, o);
        __shared__ int sred[4];
        if ((tid & 31) == 0) sred[tid >> 5] = cnt;
        __syncthreads();
        if (tid == 0) g_sum[row] = (float)(sred[0] + sred[1] + sred[2] + sred[3]);
        __threadfence();       // make g_s8 + g_sum visible before signaling
        __syncthreads();
        if (tid == 0) atomicAdd(&g_ready[r], 1);
        return;
    }

    // ---------------- gemm block: tile (ti, tj=r), split ks ----------------
    int q = rem - 128;
    int ks = q & 3;
    int ti = q >> 2;
    int tj = r;

    // wait for both rowblocks' conversions (counters accumulate across replays)
    if (tid == 0) {
        volatile int* rd = g_ready;
        while (rd[ti] < 128 || rd[tj] < 128) __nanosleep(200);
    }
    __syncthreads();
    __threadfence();          // acquire: order counter read before g_s8 reads

    uint32_t sbase = smem_u32(smem);
    int wid = tid >> 5;
    int lane = tid & 31;

    // cp.async addressing: 2048 granules per side / 128 threads = 16 each
    int row0 = tid >> 4, g0 = tid & 15;   // base granule: row row0, 16B col g0
    const char* baseA = (const char*)g_s8 + (size_t)(ti * 128 + row0) * HW + (size_t)ks * KSL + g0 * 16;
    const char* baseB = (const char*)g_s8 + (size_t)(tj * 128 + row0) * HW + (size_t)ks * KSL + g0 * 16;
    uint32_t dst0 = (uint32_t)(row0 * ROW_STRIDE + g0 * 16);

    #pragma unroll
    for (int p = 0; p < STAGES - 1; ++p) {
        uint32_t ab = sbase + p * STAGE_BYTES;
        uint32_t bb = ab + SIDE_BYTES;
        size_t cb = (size_t)p * KC_BYTES;
        #pragma unroll
        for (int qq = 0; qq < 16; ++qq) {
            CP_ASYNC16(ab + dst0 + qq * (8 * ROW_STRIDE), baseA + cb + (size_t)qq * 8 * HW);
            CP_ASYNC16(bb + dst0 + qq * (8 * ROW_STRIDE), baseB + cb + (size_t)qq * 8 * HW);
        }
        CP_COMMIT();
    }

    // warp tiling: 4 warps, 2x2 grid of 64x64 warp tiles
    int wm = wid & 1;          // row half
    int wn = wid >> 1;         // col half
    int mi = lane >> 3, lr = lane & 7;
    uint32_t a_base = sbase + (uint32_t)((wm * 64 + (mi & 1) * 8 + lr) * ROW_STRIDE + (mi >> 1) * 16);
    uint32_t b_base = sbase + SIDE_BYTES
                    + (uint32_t)((wn * 64 + (lane & 7)) * ROW_STRIDE + ((lane >> 3) & 1) * 16);

    int acc[4][8][4];
    #pragma unroll
    for (int mb = 0; mb < 4; ++mb)
        #pragma unroll
        for (int nb = 0; nb < 8; ++nb)
            #pragma unroll
            for (int c = 0; c < 4; ++c) acc[mb][nb][c] = 0;

    for (int jm = 0; jm < NC; ++jm) {
        int nxt = jm + STAGES - 1;
        if (nxt < NC) {
            uint32_t ab = sbase + (nxt % STAGES) * STAGE_BYTES;
            uint32_t bb = ab + SIDE_BYTES;
            size_t cb = (size_t)nxt * KC_BYTES;
            #pragma unroll
            for (int qq = 0; qq < 16; ++qq) {
                CP_ASYNC16(ab + dst0 + qq * (8 * ROW_STRIDE), baseA + cb + (size_t)qq * 8 * HW);
                CP_ASYNC16(bb + dst0 + qq * (8 * ROW_STRIDE), baseB + cb + (size_t)qq * 8 * HW);
            }
        }
        CP_COMMIT();
        CP_WAIT2();
        __syncthreads();

        uint32_t soff = (jm % STAGES) * STAGE_BYTES;
        #pragma unroll
        for (int ksb = 0; ksb < 8; ++ksb) {
            uint32_t k0 = ksb * 32;
            uint32_t a[4][4], b[8][2];
            #pragma unroll
            for (int mb = 0; mb < 4; ++mb)
                LDSM_X4(a[mb][0], a[mb][1], a[mb][2], a[mb][3],
                        a_base + soff + mb * (16 * ROW_STRIDE) + k0);
            #pragma unroll
            for (int nb = 0; nb < 8; ++nb)
                LDSM_X2(b[nb][0], b[nb][1],
                        b_base + soff + nb * (8 * ROW_STRIDE) + k0);
            #pragma unroll
            for (int mb = 0; mb < 4; ++mb)
                #pragma unroll
                for (int nb = 0; nb < 8; ++nb)
                    MMA_S8(acc[mb][nb], a[mb], b[nb]);
        }
        __syncthreads();
    }

    // epilogue: transpose through smem (stride 132 floats: rows 16B-aligned,
    // write-phase banks (8*(lane&3) + lane>>2) mod 32 all distinct)
    float (*sT)[T_STRIDE] = (float (*)[T_STRIDE])smem;   // 128 x 132 floats = 67.6 KB
    #pragma unroll
    for (int mb = 0; mb < 4; ++mb) {
        int rr = wm * 64 + mb * 16 + (lane >> 2);
        #pragma unroll
        for (int nb = 0; nb < 8; ++nb) {
            int c = wn * 64 + nb * 8 + (lane & 3) * 2;
            sT[c][rr]         = (float)acc[mb][nb][0];
            sT[c + 1][rr]     = (float)acc[mb][nb][1];
            sT[c][rr + 8]     = (float)acc[mb][nb][2];
            sT[c + 1][rr + 8] = (float)acc[mb][nb][3];
        }
    }
    __syncthreads();
    float* pt = g_part_T[ks];
    // 128 threads: thread c owns transposed row c (global j = tj*128+c), 32 float4
    {
        int c = tid;
        float* dstrow = pt + (size_t)(tj * 128 + c) * N_DET + ti * 128;
        #pragma unroll
        for (int k4 = 0; k4 < 32; ++k4) {
            float4 v = *(float4*)&sT[c][k4 * 4];
            *(float4*)(dstrow + k4 * 4) = v;
        }
    }
}

// ---------------------------------------------------------------------------
// decay_T[j][i] for i<j (coalesced) + comp2[j] = (max_i decay)^2 (fused colmax)
// ---------------------------------------------------------------------------
__global__ void decayT_kernel(const int* __restrict__ labels) {
    int j = blockIdx.x, tid = threadIdx.x;
    float sj = g_sum[j];
    int lj = labels[j];
    float m = 0.0f;
    for (int i = tid; i < j; i += 256) {
        size_t idx = (size_t)j * N_DET + i;
        float inter = g_part_T[0][idx] + g_part_T[1][idx] + g_part_T[2][idx] + g_part_T[3][idx];
        float d = 0.0f;
        if (labels[i] == lj) d = inter / (g_sum[i] + sj - inter);
        g_decay_T[idx] = d;
        m = fmaxf(m, d);
    }
    __shared__ float s[256];
    s[tid] = m;
    __syncthreads();
    for (int o = 128; o > 0; o >>= 1) {
        if (tid < o) s[tid] = fmaxf(s[tid], s[tid + o]);
        __syncthreads();
    }
    if (tid == 0) g_comp2[j] = s[0] * s[0];
}

// ---------------------------------------------------------------------------
// out[j] = score[j] * exp(-SIGMA * max_i(d_ij^2 - c_i^2)) (coalesced)
// ---------------------------------------------------------------------------
__global__ void final_kernel(const float* __restrict__ scores, float* __restrict__ out) {
    int j = blockIdx.x, tid = threadIdx.x;
    float m = -1e30f;
    for (int i = tid; i < N_DET; i += 256) {
        float d = (i < j) ? g_decay_T[(size_t)j * N_DET + i] : 0.0f;
        m = fmaxf(m, d * d - g_comp2[i]);
    }
    __shared__ float s[256];
    s[tid] = m;
    __syncthreads();
    for (int o = 128; o > 0; o >>= 1) {
        if (tid < o) s[tid] = fmaxf(s[tid], s[tid + o]);
        __syncthreads();
    }
    if (tid == 0) out[j] = scores[j] * expf(-SIGMA * s[0]);
}

// ---------------------------------------------------------------------------
extern "C" void kernel_launch(void* const* d_in, const int* in_sizes, int n_in,
                              void* d_out, int out_size) {
    const float* seg    = (const float*)d_in[0];
    const int*   labels = (const int*)d_in[1];
    const float* scores = (const float*)d_in[2];
    float* out = (float*)d_out;

    cudaFuncSetAttribute(fused_kernel, cudaFuncAttributeMaxDynamicSharedMemorySize, SMEM_TOTAL);

    fused_kernel<<<N_BLOCKS, 128, SMEM_TOTAL>>>(seg);
    decayT_kernel<<<N_DET, 256>>>(labels);
    final_kernel<<<N_DET, 256>>>(scores, out);
}

// round 8
// speedup vs baseline: 1.1571x; 1.1571x over previous
#include <cuda_runtime.h>
#include <stdint.h>

#define N_DET 1024
#define HW 40960
#define SIGMA 2.0f
#define KSPLIT 8
#define KSL (HW / KSPLIT)      // 5120 cols per split
#define NT 8                   // 128-row tile grid
#define STAGES 3
#define KC_BYTES 128           // s8 per row per chunk
#define NC (KSL / KC_BYTES)    // 40 chunks
#define ROW_STRIDE 144         // 128 + 16B pad -> conflict-free ldmatrix
#define SIDE_BYTES (128 * ROW_STRIDE)       // 18432
#define STAGE_BYTES (2 * SIDE_BYTES)        // 36864
#define SMEM_TOTAL (STAGES * STAGE_BYTES)   // 110592  -> 2 CTAs/SM
#define N_CONV 1024
#define N_GEMM (36 * KSPLIT)   // 288
#define N_BLOCKS (N_CONV + N_GEMM)
#define T_STRIDE 132           // transpose buffer stride (floats): 16B-aligned rows

// ---- device scratch ----
__device__ __align__(16) signed char g_s8[(size_t)N_DET * HW];     // 40 MB
__device__ float g_sum[N_DET];
__device__ float g_part_T[KSPLIT][(size_t)N_DET * N_DET];          // 32 MB, [j][i]
__device__ float g_decay_T[(size_t)N_DET * N_DET];                 // 4 MB,  [j][i]
__device__ float g_comp2[N_DET];
__device__ int   g_ready[NT];                                      // conv completion counters

// ---------------------------------------------------------------------------
__device__ __forceinline__ uint32_t smem_u32(const void* p) {
    uint32_t a;
    asm("{ .reg .u64 t; cvta.to.shared.u64 t, %1; cvt.u32.u64 %0, t; }" : "=r"(a) : "l"(p));
    return a;
}
#define CP_ASYNC16(dst, src) \
    asm volatile("cp.async.cg.shared.global [%0], [%1], 16;" :: "r"((uint32_t)(dst)), "l"(src) : "memory")
#define CP_COMMIT() asm volatile("cp.async.commit_group;" ::: "memory")
#define CP_WAIT2()  asm volatile("cp.async.wait_group 2;" ::: "memory")

#define LDSM_X4(r0, r1, r2, r3, addr) \
    asm volatile("ldmatrix.sync.aligned.m8n8.x4.shared.b16 {%0,%1,%2,%3}, [%4];" \
        : "=r"(r0), "=r"(r1), "=r"(r2), "=r"(r3) : "r"(addr))
#define LDSM_X2(r0, r1, addr) \
    asm volatile("ldmatrix.sync.aligned.m8n8.x2.shared.b16 {%0,%1}, [%2];" \
        : "=r"(r0), "=r"(r1) : "r"(addr))
#define MMA_S8(d, a, b) \
    asm volatile("mma.sync.aligned.m16n8k32.row.col.s32.s8.s8.s32 " \
        "{%0,%1,%2,%3}, {%4,%5,%6,%7}, {%8,%9}, {%0,%1,%2,%3};" \
        : "+r"((d)[0]), "+r"((d)[1]), "+r"((d)[2]), "+r"((d)[3]) \
        : "r"((a)[0]), "r"((a)[1]), "r"((a)[2]), "r"((a)[3]), "r"((b)[0]), "r"((b)[1]))

// ---------------------------------------------------------------------------
// Fused kernel: 1024 convert blocks + 288 gemm blocks, one launch, 2 CTAs/SM.
// bid order: segment r = [128 conv blocks, rows r*128..] [8*(r+1) gemm blocks]
// ---------------------------------------------------------------------------
__global__ void __launch_bounds__(128) fused_kernel(const float* __restrict__ seg) {
    extern __shared__ char smem[];
    int tid = threadIdx.x;

    // segment decode
    int bid = blockIdx.x;
    int r = 0;
    int rem = bid;
    while (rem >= 128 + KSPLIT * (r + 1)) { rem -= 128 + KSPLIT * (r + 1); ++r; }

    if (rem < 128) {
        // ---------------- convert block: one full mask row ----------------
        int row = r * 128 + rem;
        const float4* in4 = (const float4*)(seg + (size_t)row * HW);
        uint4* out = (uint4*)(g_s8 + (size_t)row * HW);
        int cnt = 0;
        #pragma unroll 4
        for (int u0 = 0; u0 < 20; ++u0) {          // 128 thr * 20 * 16 floats = 40960
            int u = u0 * 128 + tid;
            uint4 o;
            uint32_t* wp = (uint32_t*)&o;
            #pragma unroll
            for (int s = 0; s < 4; ++s) {
                float4 f = in4[u * 4 + s];
                uint32_t b0 = (f.x != 0.0f), b1 = (f.y != 0.0f),
                         b2 = (f.z != 0.0f), b3 = (f.w != 0.0f);
                cnt += b0 + b1 + b2 + b3;
                wp[s] = b0 | (b1 << 8) | (b2 << 16) | (b3 << 24);
            }
            out[u] = o;
        }
        #pragma unroll
        for (int o = 16; o; o >>= 1) cnt += __shfl_xor_sync(0xFFFFFFFFu, cnt, o);
        __shared__ int sred[4];
        if ((tid & 31) == 0) sred[tid >> 5] = cnt;
        __syncthreads();
        if (tid == 0) g_sum[row] = (float)(sred[0] + sred[1] + sred[2] + sred[3]);
        __threadfence();       // publish g_s8 + g_sum before signaling
        __syncthreads();
        if (tid == 0) atomicAdd(&g_ready[r], 1);
        return;
    }

    // ---------------- gemm block: tile (ti, tj=r), split ks ----------------
    int q = rem - 128;
    int ks = q & (KSPLIT - 1);
    int ti = q >> 3;
    int tj = r;

    // wait for both rowblocks' conversions (counters accumulate across replays)
    if (tid == 0) {
        volatile int* rd = g_ready;
        while (rd[ti] < 128 || rd[tj] < 128) __nanosleep(200);
    }
    __syncthreads();
    __threadfence();          // acquire

    uint32_t sbase = smem_u32(smem);
    int wid = tid >> 5;
    int lane = tid & 31;

    // cp.async: 1024 granules per side / 128 threads = 8 each
    // granule l = tid + q*128: row = l>>3, g = l&7
    int row0 = tid >> 3, g0 = tid & 7;
    const char* baseA = (const char*)g_s8 + (size_t)(ti * 128 + row0) * HW + (size_t)ks * KSL + g0 * 16;
    const char* baseB = (const char*)g_s8 + (size_t)(tj * 128 + row0) * HW + (size_t)ks * KSL + g0 * 16;
    uint32_t dst0 = (uint32_t)(row0 * ROW_STRIDE + g0 * 16);

    #pragma unroll
    for (int p = 0; p < STAGES - 1; ++p) {
        uint32_t ab = sbase + p * STAGE_BYTES;
        uint32_t bb = ab + SIDE_BYTES;
        size_t cb = (size_t)p * KC_BYTES;
        #pragma unroll
        for (int qq = 0; qq < 8; ++qq) {
            CP_ASYNC16(ab + dst0 + qq * (16 * ROW_STRIDE), baseA + cb + (size_t)qq * 16 * HW);
            CP_ASYNC16(bb + dst0 + qq * (16 * ROW_STRIDE), baseB + cb + (size_t)qq * 16 * HW);
        }
        CP_COMMIT();
    }

    // warp tiling: 4 warps, 2x2 grid of 64x64 warp tiles
    int wm = wid & 1;
    int wn = wid >> 1;
    int mi = lane >> 3, lr = lane & 7;
    uint32_t a_base = sbase + (uint32_t)((wm * 64 + (mi & 1) * 8 + lr) * ROW_STRIDE + (mi >> 1) * 16);
    uint32_t b_base = sbase + SIDE_BYTES
                    + (uint32_t)((wn * 64 + (lane & 7)) * ROW_STRIDE + ((lane >> 3) & 1) * 16);

    int acc[4][8][4];
    #pragma unroll
    for (int mb = 0; mb < 4; ++mb)
        #pragma unroll
        for (int nb = 0; nb < 8; ++nb)
            #pragma unroll
            for (int c = 0; c < 4; ++c) acc[mb][nb][c] = 0;

    for (int jm = 0; jm < NC; ++jm) {
        int nxt = jm + STAGES - 1;
        if (nxt < NC) {
            uint32_t ab = sbase + (nxt % STAGES) * STAGE_BYTES;
            uint32_t bb = ab + SIDE_BYTES;
            size_t cb = (size_t)nxt * KC_BYTES;
            #pragma unroll
            for (int qq = 0; qq < 8; ++qq) {
                CP_ASYNC16(ab + dst0 + qq * (16 * ROW_STRIDE), baseA + cb + (size_t)qq * 16 * HW);
                CP_ASYNC16(bb + dst0 + qq * (16 * ROW_STRIDE), baseB + cb + (size_t)qq * 16 * HW);
            }
        }
        CP_COMMIT();
        CP_WAIT2();
        __syncthreads();

        uint32_t soff = (jm % STAGES) * STAGE_BYTES;
        #pragma unroll
        for (int ksb = 0; ksb < 4; ++ksb) {        // 4 x k32 per 128B chunk
            uint32_t k0 = ksb * 32;
            uint32_t a[4][4], b[8][2];
            #pragma unroll
            for (int mb = 0; mb < 4; ++mb)
                LDSM_X4(a[mb][0], a[mb][1], a[mb][2], a[mb][3],
                        a_base + soff + mb * (16 * ROW_STRIDE) + k0);
            #pragma unroll
            for (int nb = 0; nb < 8; ++nb)
                LDSM_X2(b[nb][0], b[nb][1],
                        b_base + soff + nb * (8 * ROW_STRIDE) + k0);
            #pragma unroll
            for (int mb = 0; mb < 4; ++mb)
                #pragma unroll
                for (int nb = 0; nb < 8; ++nb)
                    MMA_S8(acc[mb][nb], a[mb], b[nb]);
        }
        __syncthreads();
    }

    // epilogue: transpose through smem (stride 132: 16B-aligned rows, conflict-free)
    float (*sT)[T_STRIDE] = (float (*)[T_STRIDE])smem;   // 128 x 132 floats = 67.6 KB
    #pragma unroll
    for (int mb = 0; mb < 4; ++mb) {
        int rr = wm * 64 + mb * 16 + (lane >> 2);
        #pragma unroll
        for (int nb = 0; nb < 8; ++nb) {
            int c = wn * 64 + nb * 8 + (lane & 3) * 2;
            sT[c][rr]         = (float)acc[mb][nb][0];
            sT[c + 1][rr]     = (float)acc[mb][nb][1];
            sT[c][rr + 8]     = (float)acc[mb][nb][2];
            sT[c + 1][rr + 8] = (float)acc[mb][nb][3];
        }
    }
    __syncthreads();
    float* pt = g_part_T[ks];
    {
        int c = tid;       // transposed row c -> global j = tj*128+c
        float* dstrow = pt + (size_t)(tj * 128 + c) * N_DET + ti * 128;
        #pragma unroll
        for (int k4 = 0; k4 < 32; ++k4) {
            float4 v = *(float4*)&sT[c][k4 * 4];
            *(float4*)(dstrow + k4 * 4) = v;
        }
    }
}

// ---------------------------------------------------------------------------
// decay_T[j][i] for i<j (coalesced) + comp2[j] = (max_i decay)^2 (fused colmax)
// ---------------------------------------------------------------------------
__global__ void decayT_kernel(const int* __restrict__ labels) {
    int j = blockIdx.x, tid = threadIdx.x;
    float sj = g_sum[j];
    int lj = labels[j];
    float m = 0.0f;
    for (int i = tid; i < j; i += 256) {
        size_t idx = (size_t)j * N_DET + i;
        float inter = 0.0f;
        #pragma unroll
        for (int k = 0; k < KSPLIT; ++k) inter += g_part_T[k][idx];
        float d = 0.0f;
        if (labels[i] == lj) d = inter / (g_sum[i] + sj - inter);
        g_decay_T[idx] = d;
        m = fmaxf(m, d);
    }
    __shared__ float s[256];
    s[tid] = m;
    __syncthreads();
    for (int o = 128; o > 0; o >>= 1) {
        if (tid < o) s[tid] = fmaxf(s[tid], s[tid + o]);
        __syncthreads();
    }
    if (tid == 0) g_comp2[j] = s[0] * s[0];
}

// ---------------------------------------------------------------------------
// out[j] = score[j] * exp(-SIGMA * max_i(d_ij^2 - c_i^2)) (coalesced)
// ---------------------------------------------------------------------------
__global__ void final_kernel(const float* __restrict__ scores, float* __restrict__ out) {
    int j = blockIdx.x, tid = threadIdx.x;
    float m = -1e30f;
    for (int i = tid; i < N_DET; i += 256) {
        float d = (i < j) ? g_decay_T[(size_t)j * N_DET + i] : 0.0f;
        m = fmaxf(m, d * d - g_comp2[i]);
    }
    __shared__ float s[256];
    s[tid] = m;
    __syncthreads();
    for (int o = 128; o > 0; o >>= 1) {
        if (tid < o) s[tid] = fmaxf(s[tid], s[tid + o]);
        __syncthreads();
    }
    if (tid == 0) out[j] = scores[j] * expf(-SIGMA * s[0]);
}

// ---------------------------------------------------------------------------
extern "C" void kernel_launch(void* const* d_in, const int* in_sizes, int n_in,
                              void* d_out, int out_size) {
    const float* seg    = (const float*)d_in[0];
    const int*   labels = (const int*)d_in[1];
    const float* scores = (const float*)d_in[2];
    float* out = (float*)d_out;

    cudaFuncSetAttribute(fused_kernel, cudaFuncAttributeMaxDynamicSharedMemorySize, SMEM_TOTAL);

    fused_kernel<<<N_BLOCKS, 128, SMEM_TOTAL>>>(seg);
    decayT_kernel<<<N_DET, 256>>>(labels);
    final_kernel<<<N_DET, 256>>>(scores, out);
}

// round 9
// speedup vs baseline: 1.3881x; 1.1996x over previous
#include <cuda_runtime.h>
#include <stdint.h>

#define N_DET 1024
#define HW 40960
#define SIGMA 2.0f
#define KSPLIT 8
#define KSL (HW / KSPLIT)      // 5120 cols per split
#define NT 8                   // 128-row tile grid
#define NTILES 36              // triu incl diag
#define STAGES 3
#define KC_BYTES 128           // s8 per row per chunk
#define NC (KSL / KC_BYTES)    // 40 chunks
#define ROW_STRIDE 144         // 128 + 16B pad -> conflict-free ldmatrix
#define SIDE_BYTES (128 * ROW_STRIDE)       // 18432
#define STAGE_BYTES (2 * SIDE_BYTES)        // 36864
#define SMEM_TOTAL (STAGES * STAGE_BYTES)   // 110592 -> 2 CTAs/SM
#define N_GEMM (NTILES * KSPLIT)            // 288
#define T_STRIDE 132           // transpose buffer stride (floats): 16B-aligned rows

// ---- device scratch ----
__device__ __align__(16) signed char g_s8[(size_t)N_DET * HW];     // 40 MB
__device__ float g_sum[N_DET];
__device__ float g_part_T[KSPLIT][(size_t)N_DET * N_DET];          // 32 MB, [j][i]
__device__ float g_decay_T[(size_t)N_DET * N_DET];                 // 4 MB,  [j][i]
__device__ float g_comp2[N_DET];

// ---------------------------------------------------------------------------
__device__ __forceinline__ uint32_t smem_u32(const void* p) {
    uint32_t a;
    asm("{ .reg .u64 t; cvta.to.shared.u64 t, %1; cvt.u32.u64 %0, t; }" : "=r"(a) : "l"(p));
    return a;
}
#define CP_ASYNC16(dst, src) \
    asm volatile("cp.async.cg.shared.global [%0], [%1], 16;" :: "r"((uint32_t)(dst)), "l"(src) : "memory")
#define CP_COMMIT() asm volatile("cp.async.commit_group;" ::: "memory")
#define CP_WAIT2()  asm volatile("cp.async.wait_group 2;" ::: "memory")

#define LDSM_X4(r0, r1, r2, r3, addr) \
    asm volatile("ldmatrix.sync.aligned.m8n8.x4.shared.b16 {%0,%1,%2,%3}, [%4];" \
        : "=r"(r0), "=r"(r1), "=r"(r2), "=r"(r3) : "r"(addr))
#define LDSM_X2(r0, r1, addr) \
    asm volatile("ldmatrix.sync.aligned.m8n8.x2.shared.b16 {%0,%1}, [%2];" \
        : "=r"(r0), "=r"(r1) : "r"(addr))
#define MMA_S8(d, a, b) \
    asm volatile("mma.sync.aligned.m16n8k32.row.col.s32.s8.s8.s32 " \
        "{%0,%1,%2,%3}, {%4,%5,%6,%7}, {%8,%9}, {%0,%1,%2,%3};" \
        : "+r"((d)[0]), "+r"((d)[1]), "+r"((d)[2]), "+r"((d)[3]) \
        : "r"((a)[0]), "r"((a)[1]), "r"((a)[2]), "r"((a)[3]), "r"((b)[0]), "r"((b)[1]))

// ---------------------------------------------------------------------------
// Kernel 1: fp32 {0,1} -> s8 {0,1} + row sums. Full occupancy (no smem cap).
// ---------------------------------------------------------------------------
__global__ void convert_kernel(const float* __restrict__ seg) {
    int r = blockIdx.x, tid = threadIdx.x;
    const float4* in4 = (const float4*)(seg + (size_t)r * HW);
    uint4* out = (uint4*)(g_s8 + (size_t)r * HW);
    int cnt = 0;
    #pragma unroll
    for (int it = 0; it < 10; ++it) {              // 256 thr * 10 * 16 floats = 40960
        uint32_t w[4];
        uint4 o;
        uint32_t* wp = (uint32_t*)&o;
        #pragma unroll
        for (int s = 0; s < 4; ++s) {
            float4 f = in4[(it * 4 + s) * 256 + tid];
            uint32_t b0 = (f.x != 0.0f), b1 = (f.y != 0.0f),
                     b2 = (f.z != 0.0f), b3 = (f.w != 0.0f);
            cnt += b0 + b1 + b2 + b3;
            wp[s] = b0 | (b1 << 8) | (b2 << 16) | (b3 << 24);
        }
        (void)w[0];
        // note: the 4 loads above are strided 256*16B apart -> all coalesced
        // output index: interleave matches input order (element i of row -> byte i)
        // out word group for (it,s): position (it*4+s)*256 + tid
        #pragma unroll
        for (int s = 0; s < 4; ++s)
            ((uint32_t*)out)[(it * 4 + s) * 256 + tid] = wp[s];
    }
    #pragma unroll
    for (int o = 16; o; o >>= 1) cnt += __shfl_xor_sync(0xFFFFFFFFu, cnt, o);
    __shared__ int s[8];
    if ((tid & 31) == 0) s[tid >> 5] = cnt;
    __syncthreads();
    if (tid == 0) {
        int t = 0;
        #pragma unroll
        for (int w = 0; w < 8; ++w) t += s[w];
        g_sum[r] = (float)t;
    }
}

// ---------------------------------------------------------------------------
// Kernel 2: s8 mma.sync GEMM, 128x128 tile/CTA, KSPLIT=8 (288 CTAs, 1 wave
// at 2 CTAs/SM). 4 warps, 64x64 warp tiles. 3-stage cp.async pipeline.
// ---------------------------------------------------------------------------
__global__ void __launch_bounds__(128) gemm_kernel() {
    extern __shared__ char smem[];
    int tid = threadIdx.x;

    int bid = blockIdx.x;
    int ks = bid & (KSPLIT - 1);
    int t = bid >> 3;
    int ti = 0;
    while (t >= NT - ti) { t -= NT - ti; ++ti; }
    int tj = ti + t;

    uint32_t sbase = smem_u32(smem);
    int wid = tid >> 5;
    int lane = tid & 31;

    // cp.async: 1024 granules per side / 128 threads = 8 each
    int row0 = tid >> 3, g0 = tid & 7;
    const char* baseA = (const char*)g_s8 + (size_t)(ti * 128 + row0) * HW + (size_t)ks * KSL + g0 * 16;
    const char* baseB = (const char*)g_s8 + (size_t)(tj * 128 + row0) * HW + (size_t)ks * KSL + g0 * 16;
    uint32_t dst0 = (uint32_t)(row0 * ROW_STRIDE + g0 * 16);

    #pragma unroll
    for (int p = 0; p < STAGES - 1; ++p) {
        uint32_t ab = sbase + p * STAGE_BYTES;
        uint32_t bb = ab + SIDE_BYTES;
        size_t cb = (size_t)p * KC_BYTES;
        #pragma unroll
        for (int qq = 0; qq < 8; ++qq) {
            CP_ASYNC16(ab + dst0 + qq * (16 * ROW_STRIDE), baseA + cb + (size_t)qq * 16 * HW);
            CP_ASYNC16(bb + dst0 + qq * (16 * ROW_STRIDE), baseB + cb + (size_t)qq * 16 * HW);
        }
        CP_COMMIT();
    }

    // warp tiling: 4 warps, 2x2 grid of 64x64 warp tiles
    int wm = wid & 1;
    int wn = wid >> 1;
    int mi = lane >> 3, lr = lane & 7;
    uint32_t a_base = sbase + (uint32_t)((wm * 64 + (mi & 1) * 8 + lr) * ROW_STRIDE + (mi >> 1) * 16);
    uint32_t b_base = sbase + SIDE_BYTES
                    + (uint32_t)((wn * 64 + (lane & 7)) * ROW_STRIDE + ((lane >> 3) & 1) * 16);

    int acc[4][8][4];
    #pragma unroll
    for (int mb = 0; mb < 4; ++mb)
        #pragma unroll
        for (int nb = 0; nb < 8; ++nb)
            #pragma unroll
            for (int c = 0; c < 4; ++c) acc[mb][nb][c] = 0;

    for (int jm = 0; jm < NC; ++jm) {
        int nxt = jm + STAGES - 1;
        if (nxt < NC) {
            uint32_t ab = sbase + (nxt % STAGES) * STAGE_BYTES;
            uint32_t bb = ab + SIDE_BYTES;
            size_t cb = (size_t)nxt * KC_BYTES;
            #pragma unroll
            for (int qq = 0; qq < 8; ++qq) {
                CP_ASYNC16(ab + dst0 + qq * (16 * ROW_STRIDE), baseA + cb + (size_t)qq * 16 * HW);
                CP_ASYNC16(bb + dst0 + qq * (16 * ROW_STRIDE), baseB + cb + (size_t)qq * 16 * HW);
            }
        }
        CP_COMMIT();
        CP_WAIT2();
        __syncthreads();

        uint32_t soff = (jm % STAGES) * STAGE_BYTES;
        #pragma unroll
        for (int ksb = 0; ksb < 4; ++ksb) {        // 4 x k32 per 128B chunk
            uint32_t k0 = ksb * 32;
            uint32_t a[4][4], b[8][2];
            #pragma unroll
            for (int mb = 0; mb < 4; ++mb)
                LDSM_X4(a[mb][0], a[mb][1], a[mb][2], a[mb][3],
                        a_base + soff + mb * (16 * ROW_STRIDE) + k0);
            #pragma unroll
            for (int nb = 0; nb < 8; ++nb)
                LDSM_X2(b[nb][0], b[nb][1],
                        b_base + soff + nb * (8 * ROW_STRIDE) + k0);
            #pragma unroll
            for (int mb = 0; mb < 4; ++mb)
                #pragma unroll
                for (int nb = 0; nb < 8; ++nb)
                    MMA_S8(acc[mb][nb], a[mb], b[nb]);
        }
        __syncthreads();
    }

    // epilogue: transpose through smem (stride 132: 16B-aligned rows, conflict-free)
    float (*sT)[T_STRIDE] = (float (*)[T_STRIDE])smem;   // 128 x 132 floats = 67.6 KB
    #pragma unroll
    for (int mb = 0; mb < 4; ++mb) {
        int rr = wm * 64 + mb * 16 + (lane >> 2);
        #pragma unroll
        for (int nb = 0; nb < 8; ++nb) {
            int c = wn * 64 + nb * 8 + (lane & 3) * 2;
            sT[c][rr]         = (float)acc[mb][nb][0];
            sT[c + 1][rr]     = (float)acc[mb][nb][1];
            sT[c][rr + 8]     = (float)acc[mb][nb][2];
            sT[c + 1][rr + 8] = (float)acc[mb][nb][3];
        }
    }
    __syncthreads();
    float* pt = g_part_T[ks];
    {
        int c = tid;       // transposed row c -> global j = tj*128+c
        float* dstrow = pt + (size_t)(tj * 128 + c) * N_DET + ti * 128;
        #pragma unroll
        for (int k4 = 0; k4 < 32; ++k4) {
            float4 v = *(float4*)&sT[c][k4 * 4];
            *(float4*)(dstrow + k4 * 4) = v;
        }
    }
}

// ---------------------------------------------------------------------------
// Kernel 3: decay_T[j][i] for i<j (coalesced) + comp2[j] (fused colmax)
// ---------------------------------------------------------------------------
__global__ void decayT_kernel(const int* __restrict__ labels) {
    int j = blockIdx.x, tid = threadIdx.x;
    float sj = g_sum[j];
    int lj = labels[j];
    float m = 0.0f;
    for (int i = tid; i < j; i += 256) {
        size_t idx = (size_t)j * N_DET + i;
        float inter = 0.0f;
        #pragma unroll
        for (int k = 0; k < KSPLIT; ++k) inter += g_part_T[k][idx];
        float d = 0.0f;
        if (labels[i] == lj) d = inter / (g_sum[i] + sj - inter);
        g_decay_T[idx] = d;
        m = fmaxf(m, d);
    }
    __shared__ float s[256];
    s[tid] = m;
    __syncthreads();
    for (int o = 128; o > 0; o >>= 1) {
        if (tid < o) s[tid] = fmaxf(s[tid], s[tid + o]);
        __syncthreads();
    }
    if (tid == 0) g_comp2[j] = s[0] * s[0];
}

// ---------------------------------------------------------------------------
// Kernel 4: out[j] = score[j] * exp(-SIGMA * max_i(d_ij^2 - c_i^2)) (coalesced)
// ---------------------------------------------------------------------------
__global__ void final_kernel(const float* __restrict__ scores, float* __restrict__ out) {
    int j = blockIdx.x, tid = threadIdx.x;
    float m = -1e30f;
    for (int i = tid; i < N_DET; i += 256) {
        float d = (i < j) ? g_decay_T[(size_t)j * N_DET + i] : 0.0f;
        m = fmaxf(m, d * d - g_comp2[i]);
    }
    __shared__ float s[256];
    s[tid] = m;
    __syncthreads();
    for (int o = 128; o > 0; o >>= 1) {
        if (tid < o) s[tid] = fmaxf(s[tid], s[tid + o]);
        __syncthreads();
    }
    if (tid == 0) out[j] = scores[j] * expf(-SIGMA * s[0]);
}

// ---------------------------------------------------------------------------
extern "C" void kernel_launch(void* const* d_in, const int* in_sizes, int n_in,
                              void* d_out, int out_size) {
    const float* seg    = (const float*)d_in[0];
    const int*   labels = (const int*)d_in[1];
    const float* scores = (const float*)d_in[2];
    float* out = (float*)d_out;

    cudaFuncSetAttribute(gemm_kernel, cudaFuncAttributeMaxDynamicSharedMemorySize, SMEM_TOTAL);

    convert_kernel<<<N_DET, 256>>>(seg);
    gemm_kernel<<<N_GEMM, 128, SMEM_TOTAL>>>();
    decayT_kernel<<<N_DET, 256>>>(labels);
    final_kernel<<<N_DET, 256>>>(scores, out);
}